// round 15
// baseline (speedup 1.0000x reference)
#include <cuda_runtime.h>
#include <math.h>

#define BB 128
#define JJ 10
#define DD 16
#define II 6400
#define KK 8
#define CC 32
#define REP 200        // capsules per channel
#define GC  16         // channel-groups per batch (2 channels per block)

__device__ float g_Sx[BB * CC * KK];         // per-channel input sums
__device__ float g_V0[BB * 160];             // iter-0 outputs
__device__ float g_V1[BB * 160];             // V0 + iter-1 outputs
__device__ float g_part1[BB * GC * 160];     // iter-1 partial s
__device__ float g_part2[BB * GC * 160];     // iter-2 partial s

__device__ __forceinline__ void cp16(float* dst, const float* src) {
    unsigned sdst = (unsigned)__cvta_generic_to_shared(dst);
    asm volatile("cp.async.cg.shared.global [%0], [%1], 16;\n" :: "r"(sdst), "l"(src));
}
__device__ __forceinline__ void cp_commit() { asm volatile("cp.async.commit_group;\n"); }
__device__ __forceinline__ void cp_wait0()  { asm volatile("cp.async.wait_group 0;\n"); }

// ---------------------------------------------------------------------------
// k_sum: Sx[b,c,k] = sum_{i in channel c} x[b,i,k].  grid (CC, BB), block 128.
// ---------------------------------------------------------------------------
__global__ __launch_bounds__(128) void k_sum(const float* __restrict__ x) {
    const int c = blockIdx.x, b = blockIdx.y, tid = threadIdx.x;
    const float4* xp = reinterpret_cast<const float4*>(
        x + ((size_t)b * II + (size_t)c * REP) * KK);   // 400 float4

    float4 a = make_float4(0.f, 0.f, 0.f, 0.f);
    for (int p = tid; p < 400; p += 128) {              // p%2 == tid%2 (fixed k-half)
        const float4 v = xp[p];
        a.x += v.x; a.y += v.y; a.z += v.z; a.w += v.w;
    }
#pragma unroll
    for (int m = 2; m <= 16; m <<= 1) {
        a.x += __shfl_xor_sync(0xffffffffu, a.x, m);
        a.y += __shfl_xor_sync(0xffffffffu, a.y, m);
        a.z += __shfl_xor_sync(0xffffffffu, a.z, m);
        a.w += __shfl_xor_sync(0xffffffffu, a.w, m);
    }
    __shared__ float sred[4][2][4];
    const int w = tid >> 5, l = tid & 31;
    if (l < 2) { sred[w][l][0] = a.x; sred[w][l][1] = a.y;
                 sred[w][l][2] = a.z; sred[w][l][3] = a.w; }
    __syncthreads();
    if (tid < KK) {
        float s = 0.f;
#pragma unroll
        for (int ww = 0; ww < 4; ++ww) s += sred[ww][tid >> 2][tid & 3];
        g_Sx[(b * CC + c) * KK + tid] = s;
    }
}

// ---------------------------------------------------------------------------
// k_v0: V0[b] = squash(0.1 * W·Sx[b] + B).  grid BB, block 256 (160 active).
// ---------------------------------------------------------------------------
__global__ __launch_bounds__(256) void k_v0(const float* __restrict__ W,
                                            const float* __restrict__ Bv) {
    const int b = blockIdx.x, tid = threadIdx.x;
    __shared__ float Ss[CC * KK];
    __shared__ float sv[160];
    __shared__ float fb[JJ];
    if (tid < CC * KK) Ss[tid] = g_Sx[b * CC * KK + tid];
    __syncthreads();
    if (tid < 160) {
        const int j = tid / DD, d = tid % DD;
        float acc = 0.f;
#pragma unroll 4
        for (int c = 0; c < CC; ++c) {
            const float4 w0 = *reinterpret_cast<const float4*>(
                W + (size_t)(j * CC + c) * 128 + d * 8);
            const float4 w1 = *reinterpret_cast<const float4*>(
                W + (size_t)(j * CC + c) * 128 + d * 8 + 4);
            const float4 s0 = *reinterpret_cast<const float4*>(Ss + c * 8);
            const float4 s1 = *reinterpret_cast<const float4*>(Ss + c * 8 + 4);
            acc = fmaf(w0.x, s0.x, acc); acc = fmaf(w0.y, s0.y, acc);
            acc = fmaf(w0.z, s0.z, acc); acc = fmaf(w0.w, s0.w, acc);
            acc = fmaf(w1.x, s1.x, acc); acc = fmaf(w1.y, s1.y, acc);
            acc = fmaf(w1.z, s1.z, acc); acc = fmaf(w1.w, s1.w, acc);
        }
        sv[tid] = 0.1f * acc + Bv[tid];
    }
    __syncthreads();
    if (tid < JJ) {
        float sq = 0.f;
#pragma unroll
        for (int d = 0; d < DD; ++d) { const float v = sv[tid * DD + d]; sq += v * v; }
        fb[tid] = sqrtf(sq) / (1.0f + sq);
    }
    __syncthreads();
    if (tid < 160) g_V0[b * 160 + tid] = sv[tid] * fb[tid / DD];
}

// ---------------------------------------------------------------------------
// k_route: one routing pass, TWO channels per block, 512 threads.
// grid (GC, BB).  Phase A single-pass; phase B 480 threads x 17-cap chunks.
// ---------------------------------------------------------------------------
__global__ __launch_bounds__(512) void k_route(const float* __restrict__ x,
                                               const float* __restrict__ W,
                                               const float* __restrict__ Vsrc,
                                               float* __restrict__ dst) {
    __shared__ float xs[3200];     // [ch][i][k]
    __shared__ float Pq[160];      // [ch][j][k]
    __shared__ float cs[4400];     // [ch][i*11 + j]
    __shared__ float part[1920];   // [chunk*40+g][4], 12 chunks
    __shared__ float Tt[160];
    __shared__ float Vs[160];

    const int gc  = blockIdx.x;
    const int b   = blockIdx.y;
    const int tid = threadIdx.x;
    const int c0  = gc * 2;
    const float* xb = x + ((size_t)b * II + (size_t)c0 * REP) * KK;

    // 800 cp16 over 512 threads
    if (tid < 512) cp16(xs + tid * 4, xb + tid * 4);
    if (tid < 288) cp16(xs + (tid + 512) * 4, xb + (tid + 512) * 4);
    cp_commit();

    if (tid < 160) Vs[tid] = Vsrc[b * 160 + tid];
    __syncthreads();

    // P[ch,j,k] = sum_d Vs[j,d] * W[j,c0+ch,d,k]
    if (tid < 160) {
        const int ch = tid / 80, r = tid % 80, j = r >> 3, k = r & 7;
        const float* Wp = W + ((size_t)(j * CC + c0 + ch)) * 128 + k;
        float acc = 0.f;
#pragma unroll
        for (int d = 0; d < DD; ++d) acc = fmaf(Vs[j * DD + d], Wp[d * 8], acc);
        Pq[ch * 80 + j * 8 + k] = acc;
    }
    cp_wait0();
    __syncthreads();

    // ---- phase A: logits + softmax -> coefs (single pass, 400 active) ----
    if (tid < 2 * REP) {
        const int ch = (tid >= REP);
        const int i  = tid - ch * REP;
        const float4 xa = *reinterpret_cast<const float4*>(xs + ch * 1600 + i * 8);
        const float4 xc = *reinterpret_cast<const float4*>(xs + ch * 1600 + i * 8 + 4);
        float logit[JJ];
#pragma unroll
        for (int j = 0; j < JJ; ++j) {
            const float4 p0 = *reinterpret_cast<const float4*>(Pq + ch * 80 + j * 8);
            const float4 p1 = *reinterpret_cast<const float4*>(Pq + ch * 80 + j * 8 + 4);
            float l = 0.f;
            l = fmaf(xa.x, p0.x, l); l = fmaf(xa.y, p0.y, l);
            l = fmaf(xa.z, p0.z, l); l = fmaf(xa.w, p0.w, l);
            l = fmaf(xc.x, p1.x, l); l = fmaf(xc.y, p1.y, l);
            l = fmaf(xc.z, p1.z, l); l = fmaf(xc.w, p1.w, l);
            logit[j] = l;
        }
        float m = logit[0];
#pragma unroll
        for (int j = 1; j < JJ; ++j) m = fmaxf(m, logit[j]);
        float e[JJ], sum = 0.f;
#pragma unroll
        for (int j = 0; j < JJ; ++j) { e[j] = __expf(logit[j] - m); sum += e[j]; }
        const float r = __fdividef(1.0f, sum);
        float* cw = cs + ch * 2200 + i * 11;
#pragma unroll
        for (int j = 0; j < JJ; ++j) cw[j] = e[j] * r;
    }
    __syncthreads();

    // ---- phase B: partial T (12 chunks x 17 capsules, 480 threads) ----
    if (tid < 480) {
        const int chunk = tid / 40, g = tid % 40;
        const int ch = g / 20, r = g % 20, j = r >> 1, kh = r & 1;
        const int i0 = chunk * 17;
        const int i1 = (i0 + 17 < REP) ? i0 + 17 : REP;
        float a0 = 0.f, a1 = 0.f, a2 = 0.f, a3 = 0.f;
        const float* xp = xs + ch * 1600 + i0 * 8 + kh * 4;
        const float* cp = cs + ch * 2200 + i0 * 11 + j;
#pragma unroll 2
        for (int i = i0; i < i1; ++i) {
            const float4 xv = *reinterpret_cast<const float4*>(xp);
            const float cf = *cp;
            a0 = fmaf(cf, xv.x, a0); a1 = fmaf(cf, xv.y, a1);
            a2 = fmaf(cf, xv.z, a2); a3 = fmaf(cf, xv.w, a3);
            xp += 8; cp += 11;
        }
        *reinterpret_cast<float4*>(part + tid * 4) = make_float4(a0, a1, a2, a3);
    }
    __syncthreads();

    // ---- phase C: combine -> Tt ----
    if (tid < 160) {
        const int ch = tid / 80, r = tid % 80, j = r >> 3, k = r & 7;
        const int g = ch * 20 + j * 2 + (k >> 2), q = k & 3;
        float t = 0.f;
#pragma unroll
        for (int chunk = 0; chunk < 12; ++chunk)
            t += part[(chunk * 40 + g) * 4 + q];
        Tt[tid] = t;
    }
    __syncthreads();

    // ---- phase D: partial s -> global ----
    if (tid < 160) {
        const int j = tid / DD, d = tid % DD;
        float sreg = 0.f;
#pragma unroll
        for (int ch = 0; ch < 2; ++ch) {
            const float4 w0 = *reinterpret_cast<const float4*>(
                W + (size_t)(j * CC + c0 + ch) * 128 + d * 8);
            const float4 w1 = *reinterpret_cast<const float4*>(
                W + (size_t)(j * CC + c0 + ch) * 128 + d * 8 + 4);
            const float4 t0 = *reinterpret_cast<const float4*>(Tt + ch * 80 + j * 8);
            const float4 t1 = *reinterpret_cast<const float4*>(Tt + ch * 80 + j * 8 + 4);
            sreg = fmaf(w0.x, t0.x, sreg); sreg = fmaf(w0.y, t0.y, sreg);
            sreg = fmaf(w0.z, t0.z, sreg); sreg = fmaf(w0.w, t0.w, sreg);
            sreg = fmaf(w1.x, t1.x, sreg); sreg = fmaf(w1.y, t1.y, sreg);
            sreg = fmaf(w1.z, t1.z, sreg); sreg = fmaf(w1.w, t1.w, sreg);
        }
        dst[((size_t)b * GC + gc) * 160 + tid] = sreg;
    }
}

// ---------------------------------------------------------------------------
// k_reduce: rv[b] = squash(sum_gc part[b] + B) combined per mode.
//   mode 0 (k_v1):   g_V1 = g_V0 + squash(...)
//   mode 1 (k_final): out = squash(...)
// grid BB, block 640: quarter q sums 4 rows -> smem, then 160 combine.
// ---------------------------------------------------------------------------
__global__ __launch_bounds__(640) void k_reduce(const float* __restrict__ part,
                                                const float* __restrict__ Bv,
                                                float* __restrict__ out, int mode) {
    const int b = blockIdx.x, tid = threadIdx.x;
    __shared__ float red[4][160];
    __shared__ float sv[160];
    __shared__ float fb[JJ];

    const int q = tid / 160, e = tid % 160;
    {
        const float* src = part + (size_t)b * GC * 160 + (size_t)q * 4 * 160 + e;
        float s = src[0] + src[160] + src[320] + src[480];
        red[q][e] = s;
    }
    __syncthreads();
    if (tid < 160) sv[tid] = Bv[tid] + ((red[0][tid] + red[1][tid]) +
                                        (red[2][tid] + red[3][tid]));
    __syncthreads();
    if (tid < JJ) {
        float sq = 0.f;
#pragma unroll
        for (int d = 0; d < DD; ++d) { const float v = sv[tid * DD + d]; sq += v * v; }
        fb[tid] = sqrtf(sq) / (1.0f + sq);
    }
    __syncthreads();
    if (tid < 160) {
        const float o = sv[tid] * fb[tid / DD];
        if (mode == 0) g_V1[b * 160 + tid] = g_V0[b * 160 + tid] + o;
        else           out[(size_t)b * 160 + tid] = o;
    }
}

// ---------------------------------------------------------------------------
extern "C" void kernel_launch(void* const* d_in, const int* in_sizes, int n_in,
                              void* d_out, int out_size) {
    const float* x  = (const float*)d_in[0];  // [128, 6400, 8]
    const float* W  = (const float*)d_in[1];  // [10, 32, 16, 8]
    const float* Bv = (const float*)d_in[2];  // [10, 16]
    float* out = (float*)d_out;               // [128, 10, 16]

    float *pV0, *pV1, *pP1, *pP2;
    cudaGetSymbolAddress((void**)&pV0, g_V0);
    cudaGetSymbolAddress((void**)&pV1, g_V1);
    cudaGetSymbolAddress((void**)&pP1, g_part1);
    cudaGetSymbolAddress((void**)&pP2, g_part2);

    const dim3 gr(GC, BB);
    k_sum<<<dim3(CC, BB), 128>>>(x);
    k_v0<<<BB, 256>>>(W, Bv);
    k_route<<<gr, 512>>>(x, W, pV0, pP1);        // iter 1
    k_reduce<<<BB, 640>>>(pP1, Bv, nullptr, 0);  // V1
    k_route<<<gr, 512>>>(x, W, pV1, pP2);        // iter 2
    k_reduce<<<BB, 640>>>(pP2, Bv, out, 1);      // final
}

// round 16
// speedup vs baseline: 1.0645x; 1.0645x over previous
#include <cuda_runtime.h>
#include <math.h>

#define BB 128
#define JJ 10
#define DD 16
#define II 6400
#define KK 8
#define CC 32
#define REP 200        // capsules per channel
#define GC  16         // channel-groups per batch (2 channels per block)

__device__ float g_Sx[BB * CC * KK];         // per-channel input sums
__device__ float g_V0[BB * 160];             // iter-0 outputs
__device__ float g_V1[BB * 160];             // V0 + iter-1 outputs
__device__ float g_part1[BB * GC * 160];     // iter-1 partial s
__device__ float g_part2[BB * GC * 160];     // iter-2 partial s

__device__ __forceinline__ void cp16(float* dst, const float* src) {
    unsigned sdst = (unsigned)__cvta_generic_to_shared(dst);
    asm volatile("cp.async.cg.shared.global [%0], [%1], 16;\n" :: "r"(sdst), "l"(src));
}
__device__ __forceinline__ void cp_commit() { asm volatile("cp.async.commit_group;\n"); }
__device__ __forceinline__ void cp_wait0()  { asm volatile("cp.async.wait_group 0;\n"); }

// ---------------------------------------------------------------------------
// k_sum: Sx[b,c,k] = sum_{i in channel c} x[b,i,k].  grid (CC, BB), block 128.
// ---------------------------------------------------------------------------
__global__ __launch_bounds__(128) void k_sum(const float* __restrict__ x) {
    const int c = blockIdx.x, b = blockIdx.y, tid = threadIdx.x;
    const float4* xp = reinterpret_cast<const float4*>(
        x + ((size_t)b * II + (size_t)c * REP) * KK);   // 400 float4

    float4 a = make_float4(0.f, 0.f, 0.f, 0.f);
    for (int p = tid; p < 400; p += 128) {              // p%2 == tid%2 (fixed k-half)
        const float4 v = xp[p];
        a.x += v.x; a.y += v.y; a.z += v.z; a.w += v.w;
    }
#pragma unroll
    for (int m = 2; m <= 16; m <<= 1) {
        a.x += __shfl_xor_sync(0xffffffffu, a.x, m);
        a.y += __shfl_xor_sync(0xffffffffu, a.y, m);
        a.z += __shfl_xor_sync(0xffffffffu, a.z, m);
        a.w += __shfl_xor_sync(0xffffffffu, a.w, m);
    }
    __shared__ float sred[4][2][4];
    const int w = tid >> 5, l = tid & 31;
    if (l < 2) { sred[w][l][0] = a.x; sred[w][l][1] = a.y;
                 sred[w][l][2] = a.z; sred[w][l][3] = a.w; }
    __syncthreads();
    if (tid < KK) {
        float s = 0.f;
#pragma unroll
        for (int ww = 0; ww < 4; ++ww) s += sred[ww][tid >> 2][tid & 3];
        g_Sx[(b * CC + c) * KK + tid] = s;
    }
}

// ---------------------------------------------------------------------------
// k_v0: V0[b] = squash(0.1 * W·Sx[b] + B).  grid BB, block 256 (160 active).
// ---------------------------------------------------------------------------
__global__ __launch_bounds__(256) void k_v0(const float* __restrict__ W,
                                            const float* __restrict__ Bv) {
    const int b = blockIdx.x, tid = threadIdx.x;
    __shared__ float Ss[CC * KK];
    __shared__ float sv[160];
    __shared__ float fb[JJ];
    if (tid < CC * KK) Ss[tid] = g_Sx[b * CC * KK + tid];
    __syncthreads();
    if (tid < 160) {
        const int j = tid / DD, d = tid % DD;
        float acc = 0.f;
#pragma unroll 4
        for (int c = 0; c < CC; ++c) {
            const float4 w0 = *reinterpret_cast<const float4*>(
                W + (size_t)(j * CC + c) * 128 + d * 8);
            const float4 w1 = *reinterpret_cast<const float4*>(
                W + (size_t)(j * CC + c) * 128 + d * 8 + 4);
            const float4 s0 = *reinterpret_cast<const float4*>(Ss + c * 8);
            const float4 s1 = *reinterpret_cast<const float4*>(Ss + c * 8 + 4);
            acc = fmaf(w0.x, s0.x, acc); acc = fmaf(w0.y, s0.y, acc);
            acc = fmaf(w0.z, s0.z, acc); acc = fmaf(w0.w, s0.w, acc);
            acc = fmaf(w1.x, s1.x, acc); acc = fmaf(w1.y, s1.y, acc);
            acc = fmaf(w1.z, s1.z, acc); acc = fmaf(w1.w, s1.w, acc);
        }
        sv[tid] = 0.1f * acc + Bv[tid];
    }
    __syncthreads();
    if (tid < JJ) {
        float sq = 0.f;
#pragma unroll
        for (int d = 0; d < DD; ++d) { const float v = sv[tid * DD + d]; sq += v * v; }
        fb[tid] = sqrtf(sq) / (1.0f + sq);
    }
    __syncthreads();
    if (tid < 160) g_V0[b * 160 + tid] = sv[tid] * fb[tid / DD];
}

// ---------------------------------------------------------------------------
// k_route: one routing pass, TWO channels per block processed SEQUENTIALLY.
// grid (GC, BB), block 256.  smem ~27KB -> 8 blocks/SM, 1.73 waves.
// ---------------------------------------------------------------------------
__global__ __launch_bounds__(256) void k_route(const float* __restrict__ x,
                                               const float* __restrict__ W,
                                               const float* __restrict__ Vsrc,
                                               float* __restrict__ dst) {
    __shared__ float xs[3200];     // [ch][i][k]  (both channels)
    __shared__ float Pq[160];      // [ch][j][k]  (both channels)
    __shared__ float cs[2200];     // [i*11 + j]  (CURRENT channel only)
    __shared__ float part[960];    // [chunk*20+g][4], 12 chunks (current channel)
    __shared__ float Tt[80];       // [j*8+k]     (current channel)
    __shared__ float Vs[160];

    const int gc  = blockIdx.x;
    const int b   = blockIdx.y;
    const int tid = threadIdx.x;
    const int c0  = gc * 2;
    const float* xb = x + ((size_t)b * II + (size_t)c0 * REP) * KK;

    for (int t = tid; t < 800; t += 256) cp16(xs + t * 4, xb + t * 4);
    cp_commit();

    if (tid < 160) Vs[tid] = Vsrc[b * 160 + tid];
    __syncthreads();

    // P[ch,j,k] = sum_d Vs[j,d] * W[j,c0+ch,d,k]  (both channels up front)
    if (tid < 160) {
        const int ch = tid / 80, r = tid % 80, j = r >> 3, k = r & 7;
        const float* Wp = W + ((size_t)(j * CC + c0 + ch)) * 128 + k;
        float acc = 0.f;
#pragma unroll
        for (int d = 0; d < DD; ++d) acc = fmaf(Vs[j * DD + d], Wp[d * 8], acc);
        Pq[ch * 80 + j * 8 + k] = acc;
    }
    cp_wait0();
    __syncthreads();           // xs + Pq ready

    float sreg = 0.f;          // per-thread (tid<160) partial s accumulator

#pragma unroll
    for (int ch = 0; ch < 2; ++ch) {
        // ---- phase A: logits + softmax for this channel (200 active) ----
        // (fused with prev channel's phase D on the ch==1 pass, see below)
        if (ch == 1 && tid < 160) {
            // phase D for ch 0: sreg += W·Tt  (Tt still holds ch0 result)
            const int j = tid / DD, d = tid % DD;
            const float4 w0 = *reinterpret_cast<const float4*>(
                W + (size_t)(j * CC + c0) * 128 + d * 8);
            const float4 w1 = *reinterpret_cast<const float4*>(
                W + (size_t)(j * CC + c0) * 128 + d * 8 + 4);
            const float4 t0 = *reinterpret_cast<const float4*>(Tt + j * 8);
            const float4 t1 = *reinterpret_cast<const float4*>(Tt + j * 8 + 4);
            sreg = fmaf(w0.x, t0.x, sreg); sreg = fmaf(w0.y, t0.y, sreg);
            sreg = fmaf(w0.z, t0.z, sreg); sreg = fmaf(w0.w, t0.w, sreg);
            sreg = fmaf(w1.x, t1.x, sreg); sreg = fmaf(w1.y, t1.y, sreg);
            sreg = fmaf(w1.z, t1.z, sreg); sreg = fmaf(w1.w, t1.w, sreg);
        }
        if (tid < REP) {
            const int i = tid;
            const float4 xa = *reinterpret_cast<const float4*>(xs + ch * 1600 + i * 8);
            const float4 xc = *reinterpret_cast<const float4*>(xs + ch * 1600 + i * 8 + 4);
            float e[JJ], sum = 0.f;
#pragma unroll
            for (int j = 0; j < JJ; ++j) {
                const float4 p0 = *reinterpret_cast<const float4*>(Pq + ch * 80 + j * 8);
                const float4 p1 = *reinterpret_cast<const float4*>(Pq + ch * 80 + j * 8 + 4);
                float l = 0.f;
                l = fmaf(xa.x, p0.x, l); l = fmaf(xa.y, p0.y, l);
                l = fmaf(xa.z, p0.z, l); l = fmaf(xa.w, p0.w, l);
                l = fmaf(xc.x, p1.x, l); l = fmaf(xc.y, p1.y, l);
                l = fmaf(xc.z, p1.z, l); l = fmaf(xc.w, p1.w, l);
                // logits bounded (|V|<=2, |u_hat|<~4): exp safe without max-sub
                e[j] = __expf(l);
                sum += e[j];
            }
            const float r = __fdividef(1.0f, sum);
            float* cw = cs + i * 11;
#pragma unroll
            for (int j = 0; j < JJ; ++j) cw[j] = e[j] * r;
        }
        __syncthreads();

        // ---- phase B: partial T (12 chunks x 17 capsules, 240 threads) ----
        if (tid < 240) {
            const int chunk = tid / 20, g = tid % 20;
            const int j = g >> 1, kh = g & 1;
            const int i0 = chunk * 17;
            const int i1 = (i0 + 17 < REP) ? i0 + 17 : REP;
            float a0 = 0.f, a1 = 0.f, a2 = 0.f, a3 = 0.f;
            const float* xp = xs + ch * 1600 + i0 * 8 + kh * 4;
            const float* cp = cs + i0 * 11 + j;
#pragma unroll 2
            for (int i = i0; i < i1; ++i) {
                const float4 xv = *reinterpret_cast<const float4*>(xp);
                const float cf = *cp;
                a0 = fmaf(cf, xv.x, a0); a1 = fmaf(cf, xv.y, a1);
                a2 = fmaf(cf, xv.z, a2); a3 = fmaf(cf, xv.w, a3);
                xp += 8; cp += 11;
            }
            *reinterpret_cast<float4*>(part + tid * 4) = make_float4(a0, a1, a2, a3);
        }
        __syncthreads();

        // ---- phase C: combine -> Tt ----
        if (tid < 80) {
            const int j = tid >> 3, k = tid & 7;
            const int g = j * 2 + (k >> 2), q = k & 3;
            float t = 0.f;
#pragma unroll
            for (int chunk = 0; chunk < 12; ++chunk)
                t += part[(chunk * 20 + g) * 4 + q];
            Tt[tid] = t;
        }
        __syncthreads();
    }

    // ---- final phase D (ch 1) + store ----
    if (tid < 160) {
        const int j = tid / DD, d = tid % DD;
        const float4 w0 = *reinterpret_cast<const float4*>(
            W + (size_t)(j * CC + c0 + 1) * 128 + d * 8);
        const float4 w1 = *reinterpret_cast<const float4*>(
            W + (size_t)(j * CC + c0 + 1) * 128 + d * 8 + 4);
        const float4 t0 = *reinterpret_cast<const float4*>(Tt + j * 8);
        const float4 t1 = *reinterpret_cast<const float4*>(Tt + j * 8 + 4);
        sreg = fmaf(w0.x, t0.x, sreg); sreg = fmaf(w0.y, t0.y, sreg);
        sreg = fmaf(w0.z, t0.z, sreg); sreg = fmaf(w0.w, t0.w, sreg);
        sreg = fmaf(w1.x, t1.x, sreg); sreg = fmaf(w1.y, t1.y, sreg);
        sreg = fmaf(w1.z, t1.z, sreg); sreg = fmaf(w1.w, t1.w, sreg);
        dst[((size_t)b * GC + gc) * 160 + tid] = sreg;
    }
}

// ---------------------------------------------------------------------------
// k_v1: V1[b] = V0[b] + squash(sum_gc g_part1[b] + B).  grid BB, block 160.
// ---------------------------------------------------------------------------
__global__ __launch_bounds__(160) void k_v1(const float* __restrict__ Bv) {
    const int b = blockIdx.x, tid = threadIdx.x;
    __shared__ float sv[160];
    __shared__ float fb[JJ];
    const float* src = g_part1 + (size_t)b * GC * 160;
    float s = Bv[tid];
#pragma unroll 8
    for (int g2 = 0; g2 < GC; ++g2) s += src[g2 * 160 + tid];
    sv[tid] = s;
    __syncthreads();
    if (tid < JJ) {
        float sq = 0.f;
#pragma unroll
        for (int d = 0; d < DD; ++d) { const float v = sv[tid * DD + d]; sq += v * v; }
        fb[tid] = sqrtf(sq) / (1.0f + sq);
    }
    __syncthreads();
    g_V1[b * 160 + tid] = g_V0[b * 160 + tid] + sv[tid] * fb[tid / DD];
}

// ---------------------------------------------------------------------------
// k_final: out[b] = squash(sum_gc g_part2[b] + B).  grid BB, block 160.
// ---------------------------------------------------------------------------
__global__ __launch_bounds__(160) void k_final(const float* __restrict__ Bv,
                                               float* __restrict__ out) {
    const int b = blockIdx.x, tid = threadIdx.x;
    __shared__ float sv[160];
    __shared__ float fb[JJ];
    const float* src = g_part2 + (size_t)b * GC * 160;
    float s = Bv[tid];
#pragma unroll 8
    for (int g2 = 0; g2 < GC; ++g2) s += src[g2 * 160 + tid];
    sv[tid] = s;
    __syncthreads();
    if (tid < JJ) {
        float sq = 0.f;
#pragma unroll
        for (int d = 0; d < DD; ++d) { const float v = sv[tid * DD + d]; sq += v * v; }
        fb[tid] = sqrtf(sq) / (1.0f + sq);
    }
    __syncthreads();
    out[(size_t)b * 160 + tid] = sv[tid] * fb[tid / DD];
}

// ---------------------------------------------------------------------------
extern "C" void kernel_launch(void* const* d_in, const int* in_sizes, int n_in,
                              void* d_out, int out_size) {
    const float* x  = (const float*)d_in[0];  // [128, 6400, 8]
    const float* W  = (const float*)d_in[1];  // [10, 32, 16, 8]
    const float* Bv = (const float*)d_in[2];  // [10, 16]
    float* out = (float*)d_out;               // [128, 10, 16]

    float *pV0, *pV1, *pP1, *pP2;
    cudaGetSymbolAddress((void**)&pV0, g_V0);
    cudaGetSymbolAddress((void**)&pV1, g_V1);
    cudaGetSymbolAddress((void**)&pP1, g_part1);
    cudaGetSymbolAddress((void**)&pP2, g_part2);

    const dim3 gr(GC, BB);
    k_sum<<<dim3(CC, BB), 128>>>(x);
    k_v0<<<BB, 256>>>(W, Bv);
    k_route<<<gr, 256>>>(x, W, pV0, pP1);    // iter 1
    k_v1<<<BB, 160>>>(Bv);
    k_route<<<gr, 256>>>(x, W, pV1, pP2);    // iter 2
    k_final<<<BB, 160>>>(Bv, out);
}